// round 11
// baseline (speedup 1.0000x reference)
#include <cuda_runtime.h>
#include <cuda_fp16.h>
#include <stdint.h>

#define BATCH   8192
#define IN_DIM  1024
#define N_HID   2048
#define OUT_DIM 256
#define S2      3072
#define NT1     8         // 1024/128 source tiles (layer1)
#define NT2     24        // 3072/128 source tiles (layer2)
#define ECAP    24        // Bin(128,.05): mean 6.4, 7.1 sigma
#define BT      64        // batch tile: 32 lanes x 2 cols

// ---- scratch (static device globals: allocation-free) ----
__device__ float    g_xT[(size_t)IN_DIM * BATCH];                 // w * x, transposed
__device__ float    g_hT[(size_t)N_HID * BATCH];                  // w * hidden, transposed
__device__ __half   g_pl[(size_t)IN_DIM * 4 * BATCH];             // 4 act planes of w*x, fp16
__device__ uint16_t g_et1[(size_t)NT1 * N_HID * ECAP];            // [tile][row][ECAP]
__device__ uint16_t g_et2[(size_t)NT2 * OUT_DIM * ECAP];
__device__ uint16_t g_ct1[(size_t)NT1 * N_HID];                   // [tile][row]
__device__ uint16_t g_ct2[(size_t)NT2 * OUT_DIM];

// ---- helpers ----
__device__ __forceinline__ void cpa16(uint32_t dst, const void* src) {
    asm volatile("cp.async.cg.shared.global [%0], [%1], 16;" :: "r"(dst), "l"(src));
}
#define CP_COMMIT() asm volatile("cp.async.commit_group;")
#define CP_WAIT0()  asm volatile("cp.async.wait_group 0;")

__device__ __forceinline__ float ftanh(float x) {
    float r; asm("tanh.approx.f32 %0, %1;" : "=f"(r) : "f"(x)); return r;
}
__device__ __forceinline__ void addp(unsigned long long& a, unsigned long long b) {
    asm("add.rn.f32x2 %0, %0, %1;" : "+l"(a) : "l"(b));
}
__device__ __forceinline__ unsigned long long f2u(float2 v) {
    unsigned long long r; asm("mov.b64 %0, {%1,%2};" : "=l"(r) : "f"(v.x), "f"(v.y)); return r;
}

// ------------------------------------------------------------------
// Build tile-major edge lists (128-wide tiles both layers).
// Entry = s_in_tile*4 + (code-1)  (<=511); kernels shift <<7 at use.
// ------------------------------------------------------------------
__global__ void build_edges_kernel(const int* __restrict__ mat) {
    int row  = blockIdx.x;
    int lane = threadIdx.x & 31, warp = threadIdx.x >> 5;  // 256 thr
    bool is2 = (row >= N_HID);
    int ntiles = is2 ? NT2 : NT1;
    int rows   = is2 ? OUT_DIM : N_HID;
    int rloc   = is2 ? row - N_HID : row;
    const int* mrow = mat + (size_t)row * S2;
    uint16_t* et = is2 ? g_et2 : g_et1;
    uint16_t* ct = is2 ? g_ct2 : g_ct1;
    unsigned lt = (1u << lane) - 1u;

    for (int t = warp; t < ntiles; t += 8) {
        int cnt = 0;
        uint16_t* dst = et + ((size_t)t * rows + rloc) * ECAP;
        for (int c = 0; c < 4; ++c) {
            int code = mrow[t * 128 + c * 32 + lane];
            unsigned m = __ballot_sync(0xffffffffu, code != 0);
            int p = cnt + __popc(m & lt);
            if (code && p < ECAP)
                dst[p] = (uint16_t)(((c * 32 + lane) << 2) | (code - 1));
            cnt += __popc(m);
        }
        if (lane == 0) ct[(size_t)t * rows + rloc] = (uint16_t)(cnt < ECAP ? cnt : ECAP);
    }
}

// ------------------------------------------------------------------
// act_kernel: transpose x, scale by w, write g_xT (fp32) + g_pl (fp16).
// ------------------------------------------------------------------
__global__ void act_kernel(const float* __restrict__ x, const float* __restrict__ wp) {
    __shared__ float tile[32][33];
    float w = *wp;
    int i0 = blockIdx.x * 32, b0 = blockIdx.y * 32;
    int tx = threadIdx.x, ty = threadIdx.y;   // 32 x 8
#pragma unroll
    for (int k = 0; k < 32; k += 8)
        tile[ty + k][tx] = w * x[(size_t)(b0 + ty + k) * IN_DIM + i0 + tx];
    __syncthreads();
#pragma unroll
    for (int k = 0; k < 32; k += 8) {
        int s = i0 + ty + k;
        int b = b0 + tx;
        float v = tile[tx][ty + k];
        g_xT[(size_t)s * BATCH + b] = v;
        size_t base = ((size_t)s * 4) * BATCH + b;
        g_pl[base]             = __float2half_rn(v);
        g_pl[base + BATCH]     = __float2half_rn(fmaxf(v, 0.0f));
        g_pl[base + 2 * BATCH] = __float2half_rn(ftanh(v));
        g_pl[base + 3 * BATCH] = __float2half_rn(fmaf(0.5f, ftanh(0.5f * v), 0.5f));
    }
}

// ------------------------------------------------------------------
// Layer 1: SRCS=128, BT=64, NODES=512 (dup=4), fp16 planes double-
// buffered, all staging via cp.async, counts preloaded to registers.
// Per edge: LDS.32 (1 crossbar phase) + cvt + f32x2 add.
// ------------------------------------------------------------------
__global__ void __launch_bounds__(1024, 1)
layer1_kernel(const float* __restrict__ wp) {
    extern __shared__ char smraw[];
    uint32_t sbase = (uint32_t)__cvta_generic_to_shared(smraw);
    // layout: pl0 64KB | pl1 64KB | ed0 24KB | ed1 24KB | cn0 1KB | cn1 1KB
    __half*   pl[2]; pl[0] = (__half*)smraw; pl[1] = pl[0] + 128 * 4 * BT;
    uint16_t* ed[2]; ed[0] = (uint16_t*)(smraw + 131072); ed[1] = ed[0] + 512 * ECAP;
    uint16_t* cn[2]; cn[0] = ed[1] + 512 * ECAP; cn[1] = cn[0] + 512;
    uint32_t pl_a[2] = { sbase, sbase + 65536 };
    uint32_t ed_a[2] = { sbase + 131072, sbase + 131072 + 24576 };
    uint32_t cn_a[2] = { sbase + 180224, sbase + 180224 + 1024 };

    int r0   = blockIdx.x * 512;
    int b0   = blockIdx.y * BT;
    int tid  = threadIdx.x;
    int warp = tid >> 5, lane = tid & 31;

#define STAGE1(TT, B)                                                                  \
    {                                                                                  \
        _Pragma("unroll")                                                              \
        for (int k = 0; k < 4; ++k) {                                                  \
            int idx = tid + (k << 10);                                                 \
            int row = idx >> 3, c = idx & 7;                                           \
            cpa16(pl_a[B] + row * 128 + c * 16,                                        \
                  g_pl + ((size_t)((TT) * 512 + row)) * BATCH + b0 + c * 8);           \
        }                                                                              \
        for (int i = tid; i < 1536; i += 1024)                                         \
            cpa16(ed_a[B] + i * 16, g_et1 + ((size_t)(TT) * N_HID + r0) * ECAP + i * 8); \
        if (tid < 64)                                                                  \
            cpa16(cn_a[B] + tid * 16, g_ct1 + (size_t)(TT) * N_HID + r0 + tid * 8);    \
    }

    STAGE1(0, 0);
    CP_COMMIT();
    CP_WAIT0();
    __syncthreads();

    unsigned long long acc[16];
#pragma unroll
    for (int n = 0; n < 16; ++n) acc[n] = 0ULL;

    for (int t = 0; t < NT1; ++t) {
        int cur = t & 1;
        if (t + 1 < NT1) { STAGE1(t + 1, cur ^ 1); }
        CP_COMMIT();

        const char*     pcur = (const char*)pl[cur] + lane * 4;
        const uint32_t* ebuf = (const uint32_t*)ed[cur];
        // preload this warp's 16 counts into registers (2x LDS.128)
        uint4 cA = *(const uint4*)(cn[cur] + warp * 16);
        uint4 cB = *(const uint4*)(cn[cur] + warp * 16 + 8);
        uint32_t cw[8] = { cA.x, cA.y, cA.z, cA.w, cB.x, cB.y, cB.z, cB.w };
#pragma unroll
        for (int n = 0; n < 16; ++n) {
            int cnt = (cw[n >> 1] >> ((n & 1) * 16)) & 0xffff;
            const uint32_t* ep = ebuf + (warp * 16 + n) * (ECAP / 2);
            int np = cnt >> 1;
            for (int j = 0; j < np; ++j) {
                uint32_t u = ep[j];
                uint32_t va = *(const uint32_t*)(pcur + ((u & 0xffffu) << 7));
                uint32_t vb = *(const uint32_t*)(pcur + ((u >> 16) << 7));
                float2 fa = __half22float2(*(const __half2*)&va);
                float2 fb = __half22float2(*(const __half2*)&vb);
                addp(acc[n], f2u(fa));
                addp(acc[n], f2u(fb));
            }
            if (cnt & 1) {
                uint32_t u = ep[np] & 0xffffu;
                uint32_t va = *(const uint32_t*)(pcur + (u << 7));
                float2 fa = __half22float2(*(const __half2*)&va);
                addp(acc[n], f2u(fa));
            }
        }
        CP_WAIT0();
        __syncthreads();
    }

    float w = *wp;
#pragma unroll
    for (int n = 0; n < 16; ++n) {
        int r = r0 + warp * 16 + n;
        float2 v = *(float2*)&acc[n];
        float2 q; q.x = w * v.x; q.y = w * v.y;
        *(float2*)&g_hT[(size_t)r * BATCH + b0 + lane * 2] = q;
    }
#undef STAGE1
}

// ------------------------------------------------------------------
// Layer 2: R10 structure but fp16 planes (1 crossbar phase per edge)
// + count preload. Fill computes acts from fp32 g_xT/g_hT, stores fp16.
// ------------------------------------------------------------------
__global__ void __launch_bounds__(1024, 1)
layer2_kernel(const float* __restrict__ wp, float* __restrict__ dout) {
    extern __shared__ char smraw[];
    uint32_t sbase = (uint32_t)__cvta_generic_to_shared(smraw);
    __half*   planes = (__half*)smraw;                          // 64KB
    uint16_t* ed[2]; ed[0] = (uint16_t*)(smraw + 65536); ed[1] = ed[0] + 256 * ECAP;
    uint16_t* cn[2]; cn[0] = ed[1] + 256 * ECAP;         cn[1] = cn[0] + 256;
    uint32_t ed_a[2] = { sbase + 65536, sbase + 65536 + 12288 };
    uint32_t cn_a[2] = { sbase + 90112, sbase + 90112 + 512 };

    int b0   = blockIdx.x * BT;
    int r0   = blockIdx.y * 256;
    int tid  = threadIdx.x;
    int warp = tid >> 5, lane = tid & 31;

#define STAGE2(TT, B)                                                                  \
    {                                                                                  \
        if (tid < 768)                                                                 \
            cpa16(ed_a[B] + tid * 16,                                                  \
                  g_et2 + ((size_t)(TT) * OUT_DIM + r0) * ECAP + tid * 8);             \
        if (tid < 32)                                                                  \
            cpa16(cn_a[B] + tid * 16, g_ct2 + (size_t)(TT) * OUT_DIM + r0 + tid * 8);  \
    }

    STAGE2(0, 0);
    CP_COMMIT();

    unsigned long long acc[8];
#pragma unroll
    for (int n = 0; n < 8; ++n) acc[n] = 0ULL;

    float4 pf[2];
#define LOADF2(T)                                                                \
    {                                                                            \
        _Pragma("unroll")                                                        \
        for (int k = 0; k < 2; ++k) {                                            \
            int idx = tid + (k << 10);                                           \
            int ls = idx >> 4, c4 = (idx & 15) << 2;                             \
            int s0 = (T) * 128;                                                  \
            const float* gb = (s0 < IN_DIM)                                      \
                ? g_xT + (size_t)s0 * BATCH                                      \
                : g_hT + (size_t)(s0 - IN_DIM) * BATCH;                          \
            pf[k] = __ldg((const float4*)(gb + (size_t)ls * BATCH + b0 + c4));   \
        }                                                                        \
    }

    LOADF2(0);
    CP_WAIT0();
    __syncthreads();

    const char* pbase = (const char*)planes + lane * 4;

    for (int t = 0; t < NT2; ++t) {
        int cur = t & 1;
        // ---- fill planes(t): compute acts, store fp16 ----
#pragma unroll
        for (int k = 0; k < 2; ++k) {
            int idx = tid + (k << 10);
            int ls = idx >> 4, c4 = (idx & 15) << 2;
            float4 xv = pf[k];
            float2 lo = { xv.x, xv.y }, hi = { xv.z, xv.w };
            float2 r1 = { fmaxf(xv.x, 0.0f), fmaxf(xv.y, 0.0f) };
            float2 r2 = { fmaxf(xv.z, 0.0f), fmaxf(xv.w, 0.0f) };
            float2 t1 = { ftanh(xv.x), ftanh(xv.y) };
            float2 t2 = { ftanh(xv.z), ftanh(xv.w) };
            float2 s1 = { fmaf(0.5f, ftanh(0.5f * xv.x), 0.5f), fmaf(0.5f, ftanh(0.5f * xv.y), 0.5f) };
            float2 s2 = { fmaf(0.5f, ftanh(0.5f * xv.z), 0.5f), fmaf(0.5f, ftanh(0.5f * xv.w), 0.5f) };
            __half* pr = planes + (ls * 4) * BT + c4;
            ((__half2*)pr)[0]            = __float22half2_rn(lo);
            ((__half2*)pr)[1]            = __float22half2_rn(hi);
            ((__half2*)(pr + BT))[0]     = __float22half2_rn(r1);
            ((__half2*)(pr + BT))[1]     = __float22half2_rn(r2);
            ((__half2*)(pr + 2 * BT))[0] = __float22half2_rn(t1);
            ((__half2*)(pr + 2 * BT))[1] = __float22half2_rn(t2);
            ((__half2*)(pr + 3 * BT))[0] = __float22half2_rn(s1);
            ((__half2*)(pr + 3 * BT))[1] = __float22half2_rn(s2);
        }
        if (t + 1 < NT2) { STAGE2(t + 1, cur ^ 1); }
        CP_COMMIT();
        __syncthreads();   // planes(t) ready

        if (t + 1 < NT2) LOADF2(t + 1);

        const uint32_t* ebuf = (const uint32_t*)ed[cur];
        uint4 c4p = *(const uint4*)(cn[cur] + warp * 8);
        uint32_t cw[4] = { c4p.x, c4p.y, c4p.z, c4p.w };
#pragma unroll
        for (int n = 0; n < 8; ++n) {
            int cnt = (cw[n >> 1] >> ((n & 1) * 16)) & 0xffff;
            const uint32_t* ep = ebuf + (warp * 8 + n) * (ECAP / 2);
            int np = cnt >> 1;
            for (int j = 0; j < np; ++j) {
                uint32_t u = ep[j];
                uint32_t va = *(const uint32_t*)(pbase + ((u & 0xffffu) << 7));
                uint32_t vb = *(const uint32_t*)(pbase + ((u >> 16) << 7));
                float2 fa = __half22float2(*(const __half2*)&va);
                float2 fb = __half22float2(*(const __half2*)&vb);
                addp(acc[n], f2u(fa));
                addp(acc[n], f2u(fb));
            }
            if (cnt & 1) {
                uint32_t u = ep[np] & 0xffffu;
                uint32_t va = *(const uint32_t*)(pbase + (u << 7));
                float2 fa = __half22float2(*(const __half2*)&va);
                addp(acc[n], f2u(fa));
            }
        }
        CP_WAIT0();
        __syncthreads();   // edge(t) done, planes free; edges(t+1) landed
    }

#pragma unroll
    for (int n = 0; n < 8; ++n) {
        int r = r0 + warp * 8 + n;
        float2 v = *(float2*)&acc[n];
        dout[(size_t)(b0 + lane * 2 + 0) * OUT_DIM + r] = v.x;
        dout[(size_t)(b0 + lane * 2 + 1) * OUT_DIM + r] = v.y;
    }
#undef STAGE2
#undef LOADF2
}

#define SMEM_L1 (131072 + 2 * 512 * ECAP * 2 + 2 * 512 * 2)   // 182272
#define SMEM_L2 (65536 + 2 * 256 * ECAP * 2 + 2 * 256 * 2)    // 91136

extern "C" void kernel_launch(void* const* d_in, const int* in_sizes, int n_in,
                              void* d_out, int out_size) {
    const float* x   = (const float*)d_in[0];
    const float* wp  = (const float*)d_in[1];
    const int*   mat = (const int*)d_in[2];
    float*       out = (float*)d_out;

    cudaFuncSetAttribute(layer1_kernel, cudaFuncAttributeMaxDynamicSharedMemorySize, SMEM_L1);
    cudaFuncSetAttribute(layer2_kernel, cudaFuncAttributeMaxDynamicSharedMemorySize, SMEM_L2);

    build_edges_kernel<<<N_HID + OUT_DIM, 256>>>(mat);
    act_kernel<<<dim3(IN_DIM / 32, BATCH / 32), dim3(32, 8)>>>(x, wp);

    // L1: grid (row-tiles=4, batch=128); adjacent bids share batch-tile
    layer1_kernel<<<dim3(N_HID / 512, BATCH / BT), 1024, SMEM_L1>>>(wp);

    // L2: grid (batch=128, 1)
    layer2_kernel<<<dim3(BATCH / BT, OUT_DIM / 256), 1024, SMEM_L2>>>(wp, out);
}